// round 9
// baseline (speedup 1.0000x reference)
#include <cuda_runtime.h>
#include <cuda_fp16.h>
#include <cstdint>

#define IN_F   4096
#define OUT_F  4096
#define BATCH  128
#define KSPLIT 8
#define NTILES 32
#define KC     (IN_F / KSPLIT)     // 512 K per CTA
#define CK     32                  // K per chunk
#define NCHUNK (KC / CK)           // 16
#define TSTRIDE 80                 // smem row stride (bytes): 64B data + 16B pad
#define TILE_B  (128 * TSTRIDE)    // 10240 B per 128x32 fp16 tile
#define STAGE_B (2 * TILE_B)       // A + B tile
#define STAGES  4
#define SMEM_TOTAL (STAGES * STAGE_B)  // 81920 B per CTA (2 CTAs/SM = 160 KB)

// ===================== device scratch =====================
__device__ __align__(16) __half g_Wh[(size_t)OUT_F * IN_F];             // 32 MB dense fp16 W (zero invariant)
__device__ __align__(16) __half g_Ah[(size_t)BATCH * IN_F];             // 1 MB fp16 A
__device__ __align__(16) float  g_part[(size_t)KSPLIT * BATCH * OUT_F]; // 16 MB K-split partials
__device__ int g_cnt[NTILES];                                           // per-n-tile arrival counters

// ===================== helpers =====================
__device__ __forceinline__ uint32_t smem_u32(const void* p) {
    uint32_t a;
    asm("{ .reg .u64 t; cvta.to.shared.u64 t, %1; cvt.u32.u64 %0, t; }" : "=r"(a) : "l"(p));
    return a;
}
__device__ __forceinline__ void ldsm4(uint32_t* r, uint32_t addr) {
    asm volatile("ldmatrix.sync.aligned.m8n8.x4.shared.b16 {%0,%1,%2,%3}, [%4];"
                 : "=r"(r[0]), "=r"(r[1]), "=r"(r[2]), "=r"(r[3]) : "r"(addr));
}
__device__ __forceinline__ void mma_fp16(float* d, const uint32_t* a, const uint32_t* b) {
    asm volatile(
        "mma.sync.aligned.m16n8k16.row.col.f32.f16.f16.f32 "
        "{%0,%1,%2,%3}, {%4,%5,%6,%7}, {%8,%9}, {%0,%1,%2,%3};"
        : "+f"(d[0]), "+f"(d[1]), "+f"(d[2]), "+f"(d[3])
        : "r"(a[0]), "r"(a[1]), "r"(a[2]), "r"(a[3]), "r"(b[0]), "r"(b[1]));
}
__device__ __forceinline__ void cp_async16(uint32_t dst, const void* src) {
    asm volatile("cp.async.cg.shared.global [%0], [%1], 16;" :: "r"(dst), "l"(src) : "memory");
}
#define CP_COMMIT() asm volatile("cp.async.commit_group;" ::: "memory")
#define CP_WAIT(n)  asm volatile("cp.async.wait_group %0;" :: "n"(n) : "memory")

// ===================== kernel 1: convert A fp32 -> fp16 (+ zero counters) =====================
__global__ void k_convertA(const float* __restrict__ inp) {
    int i = blockIdx.x * blockDim.x + threadIdx.x;   // over (128*4096)/4 = 131072
    if (blockIdx.x == 0 && threadIdx.x < NTILES) g_cnt[threadIdx.x] = 0;
    float4 v = ((const float4*)inp)[i];
    __half2 a = __floats2half2_rn(v.x, v.y);
    __half2 b = __floats2half2_rn(v.z, v.w);
    uint2 u;
    u.x = *reinterpret_cast<uint32_t*>(&a);
    u.y = *reinterpret_cast<uint32_t*>(&b);
    ((uint2*)g_Ah)[i] = u;
}

// ===================== kernel 2: scatter-add COO -> dense fp16 W =====================
__global__ void k_scatter(const int* __restrict__ rows, const int* __restrict__ cols,
                          const float* __restrict__ vals, int n) {
    int stride = gridDim.x * blockDim.x;
    for (int i = blockIdx.x * blockDim.x + threadIdx.x; i < n; i += stride)
        atomicAdd(&g_Wh[(size_t)rows[i] * IN_F + cols[i]], __float2half(vals[i]));
}

// ===================== kernel 3: fp16 GEMM + fused K-split reduction =====================
// grid (32 n-tiles, 8 k-splits), 256 threads, 2 CTAs/SM, single wave (256 <= 296).
__global__ void __launch_bounds__(256, 2) k_gemm(const float* __restrict__ bias,
                                                 float* __restrict__ out) {
    extern __shared__ char smem[];
    __shared__ int s_last;
    const uint32_t sb = smem_u32(smem);

    const int tid  = threadIdx.x;
    const int wid  = tid >> 5;
    const int lane = tid & 31;
    const int n0   = blockIdx.x * 128;
    const int kbase = blockIdx.y * KC;

    const int wm = (wid >> 2) * 64;   // warp m offset (0 / 64)
    const int wn = (wid & 3) * 32;    // warp n offset (0/32/64/96)

    float acc[4][4][4];
    #pragma unroll
    for (int i = 0; i < 4; i++)
        #pragma unroll
        for (int j = 0; j < 4; j++)
            #pragma unroll
            for (int c = 0; c < 4; c++) acc[i][j][c] = 0.f;

    // per-thread load mapping: 2 threads per row, 32B (16 halves) each
    const int r = tid >> 1;
    const int q = tid & 1;
    const __half* gA = g_Ah + (size_t)r * IN_F + kbase + q * 16;
    const __half* gB = g_Wh + (size_t)(n0 + r) * IN_F + kbase + q * 16;
    const uint32_t sts_off = (uint32_t)r * TSTRIDE + q * 32;

    // ---- prologue: issue chunks 0..STAGES-2 ----
    #pragma unroll
    for (int s = 0; s < STAGES - 1; s++) {
        const uint32_t st = sb + (uint32_t)s * STAGE_B;
        cp_async16(st + sts_off,               gA + s * CK);
        cp_async16(st + sts_off + 16,          gA + s * CK + 8);
        cp_async16(st + TILE_B + sts_off,      gB + s * CK);
        cp_async16(st + TILE_B + sts_off + 16, gB + s * CK + 8);
        CP_COMMIT();
    }

    // ldmatrix per-lane offsets (validated layout)
    const uint32_t a_off = (uint32_t)(wm + (lane & 15)) * TSTRIDE + (lane >> 4) * 16;
    const uint32_t b_off = (uint32_t)(wn + (lane & 7) + ((lane >> 4) & 1) * 8) * TSTRIDE
                         + ((lane >> 3) & 1) * 16;

    const uint4 z4 = make_uint4(0u, 0u, 0u, 0u);

    #pragma unroll 1
    for (int c = 0; c < NCHUNK; c++) {
        CP_WAIT(STAGES - 2);
        // re-zero the W bytes this thread just loaded (own-thread ordering suffices)
        *(uint4*)(gB + c * CK)     = z4;
        *(uint4*)(gB + c * CK + 8) = z4;
        __syncthreads();   // all warps done with MMA on the stage being refilled

        if (c + STAGES - 1 < NCHUNK) {
            const int cn = c + STAGES - 1;
            const uint32_t st = sb + (uint32_t)(cn & (STAGES - 1)) * STAGE_B;
            cp_async16(st + sts_off,               gA + cn * CK);
            cp_async16(st + sts_off + 16,          gA + cn * CK + 8);
            cp_async16(st + TILE_B + sts_off,      gB + cn * CK);
            cp_async16(st + TILE_B + sts_off + 16, gB + cn * CK + 8);
        }
        CP_COMMIT();   // unconditional: uniform group counting

        // ---- MMA on stage c ----
        const uint32_t st = sb + (uint32_t)(c & (STAGES - 1)) * STAGE_B;
        const uint32_t At = st, Bt = st + TILE_B;
        #pragma unroll
        for (int ks = 0; ks < 2; ks++) {
            uint32_t ah[16], bh[8];
            #pragma unroll
            for (int i = 0; i < 4; i++)
                ldsm4(ah + 4 * i, At + a_off + i * (16 * TSTRIDE) + ks * 32);
            #pragma unroll
            for (int j = 0; j < 2; j++)
                ldsm4(bh + 4 * j, Bt + b_off + j * (16 * TSTRIDE) + ks * 32);
            #pragma unroll
            for (int i = 0; i < 4; i++) {
                #pragma unroll
                for (int jn = 0; jn < 4; jn++) {
                    const uint32_t* bp = bh + (jn >> 1) * 4 + (jn & 1) * 2;
                    mma_fp16(acc[i][jn], ah + 4 * i, bp);
                }
            }
        }
    }

    // ---- write K-split partials ----
    float* po = g_part + (size_t)blockIdx.y * BATCH * OUT_F + n0;
    #pragma unroll
    for (int i = 0; i < 4; i++) {
        const int m = wm + i * 16 + (lane >> 2);
        #pragma unroll
        for (int jn = 0; jn < 4; jn++) {
            const int n = wn + jn * 8 + (lane & 3) * 2;
            float2 v0 = make_float2(acc[i][jn][0], acc[i][jn][1]);
            float2 v1 = make_float2(acc[i][jn][2], acc[i][jn][3]);
            *(float2*)(po + (size_t)m * OUT_F + n)       = v0;
            *(float2*)(po + (size_t)(m + 8) * OUT_F + n) = v1;
        }
    }

    // ---- last CTA per n-tile reduces partials + bias -> out ----
    __threadfence();
    __syncthreads();
    if (tid == 0) {
        int old = atomicAdd(&g_cnt[blockIdx.x], 1);
        s_last = (old == KSPLIT - 1);
    }
    __syncthreads();
    if (!s_last) return;
    __threadfence();

    const float4* p4 = (const float4*)g_part;
    const float4* b4 = (const float4*)bias;
    float4*       o4 = (float4*)out;
    const int nq0 = n0 >> 2;               // float4 column base
    #pragma unroll 1
    for (int it = 0; it < 16; it++) {
        const int idx = it * 256 + tid;    // 0..4095 over (128 m) x (32 q)
        const int m  = idx >> 5;
        const int nq = idx & 31;
        const size_t base = (size_t)m * (OUT_F / 4) + nq0 + nq;
        float4 s = b4[nq0 + nq];
        #pragma unroll
        for (int sp = 0; sp < KSPLIT; sp++) {
            float4 v = p4[(size_t)sp * (BATCH * OUT_F / 4) + base];
            s.x += v.x; s.y += v.y; s.z += v.z; s.w += v.w;
        }
        o4[base] = s;
    }
}

// ===================== launch =====================
extern "C" void kernel_launch(void* const* d_in, const int* in_sizes, int n_in,
                              void* d_out, int out_size) {
    const float* inp    = (const float*)d_in[0];   // [B, IN_F]
    const float* w_vals = (const float*)d_in[1];   // [nnz]
    const int*   w_rows = (const int*)  d_in[2];   // [nnz]
    const int*   w_cols = (const int*)  d_in[3];   // [nnz]
    const float* bias   = (const float*)d_in[4];   // [OUT_F]
    float*       out    = (float*)d_out;           // [B, OUT_F]
    const int n = in_sizes[1];

    cudaFuncSetAttribute(k_gemm, cudaFuncAttributeMaxDynamicSharedMemorySize, SMEM_TOTAL);

    k_convertA<<<(BATCH * IN_F / 4) / 256, 256>>>(inp);
    k_scatter<<<2048, 256>>>(w_rows, w_cols, w_vals, n);
    k_gemm<<<dim3(NTILES, KSPLIT), 256, SMEM_TOTAL>>>(bias, out);
}